// round 2
// baseline (speedup 1.0000x reference)
#include <cuda_runtime.h>
#include <math.h>

#define HID   64
#define HEADS 4
#define HDIM  16
#define NMOL  2048
#define NPROT 4096
#define EMOL  32768
#define EPROT 131072
#define BB    32
#define SPLITS 4
#define QT    128   // queries per flash block
#define KT    64    // key tile

// ---------------- scratch (device globals; no allocation allowed) ------------
__device__ float g_xm[NMOL*HID];
__device__ float g_xp[NPROT*HID];
__device__ float g_em[EMOL*HID];
__device__ float g_ep[EPROT*HID];
__device__ float g_hm[NMOL*HID];    // GINE agg/h buffer, later H_mol
__device__ float g_hp[NPROT*HID];   // GINE agg/h buffer, later H_prot
__device__ float g_q[NPROT*HID];
__device__ float g_k[NPROT*HID];
__device__ float g_v[NPROT*HID];
__device__ float g_part[(size_t)NPROT*HEADS*SPLITS*18];
__device__ float g_pool[BB*2*HID];
__device__ float g_cnt[2*BB];

// ---------------- generic linear: out[n][f] = b[f] + sum_k in[n][k]*W[k][f] --
__global__ void linear_kernel(const float* __restrict__ in, const float* __restrict__ W,
                              const float* __restrict__ b, float* __restrict__ out,
                              int N, int K) {
    int idx = blockIdx.x*blockDim.x + threadIdx.x;
    if (idx >= N*HID) return;
    int n = idx >> 6, f = idx & 63;
    float acc = b[f];
    const float* inr = in + (size_t)n*K;
    for (int k = 0; k < K; k++) acc = fmaf(inr[k], W[k*HID + f], acc);
    out[idx] = acc;
}

// ---------------- copy (h init = x, so agg lands on top of residual) ---------
__global__ void copy_kernel(float* __restrict__ dst, const float* __restrict__ src, int n) {
    int i = blockIdx.x*blockDim.x + threadIdx.x;
    if (i < n) dst[i] = src[i];
}

__global__ void zero_kernel(float* __restrict__ p, int n) {
    int i = blockIdx.x*blockDim.x + threadIdx.x;
    if (i < n) p[i] = 0.f;
}

// ---------------- GINE message + scatter-add ---------------------------------
__global__ void msg_kernel(const float* __restrict__ x, const float* __restrict__ e,
                           const int* __restrict__ ei, float* __restrict__ h, int E) {
    int idx = blockIdx.x*blockDim.x + threadIdx.x;
    if (idx >= E*HID) return;
    int ed = idx >> 6, f = idx & 63;
    int s = ei[ed], d = ei[E + ed];
    float v = x[s*HID + f] + e[idx];
    v = fmaxf(v, 0.f);
    atomicAdd(&h[d*HID + f], v);
}

// ---------------- GINE inner MLP: x = relu(relu(h@W1+b1)@W2+b2) --------------
#define MLP_ROWS 16
__global__ void gine_mlp(const float* __restrict__ h,
                         const float* __restrict__ W1, const float* __restrict__ b1,
                         const float* __restrict__ W2, const float* __restrict__ b2,
                         float* __restrict__ xout, int N) {
    __shared__ float w1s[64][64];
    __shared__ float w2s[64][64];
    __shared__ float hs[4][64];
    __shared__ float ts[4][64];
    int tid = threadIdx.x;               // 256 threads
    for (int i = tid; i < 64*64; i += 256) { w1s[i>>6][i&63] = W1[i]; w2s[i>>6][i&63] = W2[i]; }
    __syncthreads();
    int f = tid & 63, r = tid >> 6;      // r in 0..3
    float bb1 = b1[f], bb2 = b2[f];
    int base = blockIdx.x * MLP_ROWS;
    for (int rr = 0; rr < MLP_ROWS; rr += 4) {
        int row = base + rr + r;
        if (row < N) hs[r][f] = h[(size_t)row*HID + f];
        __syncthreads();
        float acc = bb1;
        #pragma unroll
        for (int k = 0; k < 64; k++) acc = fmaf(hs[r][k], w1s[k][f], acc);
        ts[r][f] = fmaxf(acc, 0.f);
        __syncthreads();
        float acc2 = bb2;
        #pragma unroll
        for (int k = 0; k < 64; k++) acc2 = fmaf(ts[r][k], w2s[k][f], acc2);
        if (row < N) xout[(size_t)row*HID + f] = fmaxf(acc2, 0.f);
        __syncthreads();
    }
}

// ---------------- flash attention, split-KV partials -------------------------
// grid: (ceil(Nq/QT), HEADS, SPLITS). One query per thread.
__global__ void flash_partial(const float* __restrict__ Q, const float* __restrict__ K,
                              const float* __restrict__ V, int Nq, int Nk, int chunk,
                              float* __restrict__ part) {
    __shared__ float sk[KT][HDIM];
    __shared__ float sv[KT][HDIM];
    int h  = blockIdx.y;
    int sp = blockIdx.z;
    int q  = blockIdx.x*QT + threadIdx.x;
    int k0 = sp*chunk;
    int k1 = min(k0 + chunk, Nk);
    bool valid = q < Nq;
    float qr[HDIM];
    if (valid) {
        const float4* qp = (const float4*)(Q + (size_t)q*HID + h*HDIM);
        #pragma unroll
        for (int i = 0; i < 4; i++) {
            float4 t = qp[i];
            qr[4*i]=t.x; qr[4*i+1]=t.y; qr[4*i+2]=t.z; qr[4*i+3]=t.w;
        }
    }
    float m = -1e30f, l = 0.f;
    float o[HDIM];
    #pragma unroll
    for (int i = 0; i < HDIM; i++) o[i] = 0.f;
    const float scale = 0.25f;   // 1/sqrt(16)

    for (int kt = k0; kt < k1; kt += KT) {
        __syncthreads();
        for (int idx = threadIdx.x; idx < KT*4; idx += QT) {
            int row = idx >> 2, c = idx & 3;
            const float4* kg = (const float4*)(K + (size_t)(kt+row)*HID + h*HDIM);
            const float4* vg = (const float4*)(V + (size_t)(kt+row)*HID + h*HDIM);
            ((float4*)(&sk[row][0]))[c] = kg[c];
            ((float4*)(&sv[row][0]))[c] = vg[c];
        }
        __syncthreads();
        if (valid) {
            #pragma unroll 4
            for (int jj = 0; jj < KT; jj++) {
                const float* kk = sk[jj];
                float s = 0.f;
                #pragma unroll
                for (int i = 0; i < HDIM; i++) s = fmaf(qr[i], kk[i], s);
                s *= scale;
                if (s > m) {
                    float alpha = __expf(m - s);
                    l *= alpha;
                    #pragma unroll
                    for (int i = 0; i < HDIM; i++) o[i] *= alpha;
                    m = s;
                }
                float p = __expf(s - m);
                l += p;
                const float* vv = sv[jj];
                #pragma unroll
                for (int i = 0; i < HDIM; i++) o[i] = fmaf(p, vv[i], o[i]);
            }
        }
    }
    if (valid) {
        float* pp = part + (((size_t)q*HEADS + h)*SPLITS + sp)*18;
        pp[0] = m; pp[1] = l;
        #pragma unroll
        for (int i = 0; i < HDIM; i++) pp[2+i] = o[i];
    }
}

// ---------------- combine split-KV partials + residual -----------------------
__global__ void attn_combine(const float* __restrict__ part, const float* __restrict__ x,
                             float* __restrict__ H, int Nq) {
    int idx = blockIdx.x*blockDim.x + threadIdx.x;    // (q, head)
    if (idx >= Nq*HEADS) return;
    int q = idx / HEADS, h = idx % HEADS;
    const float* pp = part + (size_t)idx*SPLITS*18;
    float M = -1e30f;
    for (int sp = 0; sp < SPLITS; sp++) M = fmaxf(M, pp[sp*18]);
    float L = 0.f;
    float O[HDIM];
    #pragma unroll
    for (int i = 0; i < HDIM; i++) O[i] = 0.f;
    for (int sp = 0; sp < SPLITS; sp++) {
        float w = __expf(pp[sp*18] - M);
        L += w * pp[sp*18 + 1];
        #pragma unroll
        for (int i = 0; i < HDIM; i++) O[i] = fmaf(w, pp[sp*18 + 2 + i], O[i]);
    }
    float inv = 1.f / L;
    #pragma unroll
    for (int i = 0; i < HDIM; i++)
        H[(size_t)q*HID + h*HDIM + i] = x[(size_t)q*HID + h*HDIM + i] + O[i]*inv;
}

// ---------------- batched mean-pool (scatter) --------------------------------
__global__ void pool_kernel(const float* __restrict__ H, const int* __restrict__ batch,
                            float* __restrict__ pool, float* __restrict__ cnt,
                            int N, int colofs) {
    int idx = blockIdx.x*blockDim.x + threadIdx.x;
    if (idx >= N*HID) return;
    int n = idx >> 6, f = idx & 63;
    int b = batch[n];
    atomicAdd(&pool[b*(2*HID) + colofs + f], H[idx]);
    if (f == 0) atomicAdd(&cnt[b], 1.f);
}

// ---------------- head MLP: z@fc1 relu @fc2 sigmoid --------------------------
__global__ void final_kernel(const float* __restrict__ pool, const float* __restrict__ cnt,
                             const float* __restrict__ fc1W, const float* __restrict__ fc1b,
                             const float* __restrict__ fc2W, const float* __restrict__ fc2b,
                             float* __restrict__ out) {
    __shared__ float zs[BB][2*HID];
    int b = threadIdx.y;       // 32 warps, one per batch element
    int lane = threadIdx.x;
    float cm = fmaxf(cnt[b],      1.f);
    float cp = fmaxf(cnt[BB + b], 1.f);
    for (int k = lane; k < 2*HID; k += 32) {
        float v = pool[b*(2*HID) + k];
        zs[b][k] = v / (k < HID ? cm : cp);
    }
    __syncwarp();
    float res = 0.f;
    for (int f0 = 0; f0 < HID; f0 += 32) {
        int f = f0 + lane;
        float acc = fc1b[f];
        for (int k = 0; k < 2*HID; k++) acc = fmaf(zs[b][k], fc1W[k*HID + f], acc);
        res += fmaxf(acc, 0.f) * fc2W[f];
    }
    #pragma unroll
    for (int off = 16; off; off >>= 1) res += __shfl_down_sync(0xffffffffu, res, off);
    if (lane == 0) out[b] = 1.f / (1.f + __expf(-(res + fc2b[0])));
}

// =============================================================================
extern "C" void kernel_launch(void* const* d_in, const int* in_sizes, int n_in,
                              void* d_out, int out_size) {
    // --- input ordering: reference-signature order vs setup_inputs dict order.
    // signature order: in_sizes[4] = node_lin_mol_W = 11*64 = 704
    // setup order:     in_sizes[4] = mol_edge_index = 2*32768 = 65536
    static const int sig_map[32]   = { 0,1,2,3, 4,5,6,7, 8,9,10,11, 12,13,14,15,
                                       16,17,18,19, 20,21,22,23, 24,25,26,27, 28,29,30,31 };
    static const int setup_map[32] = { 0,1,2,3, 8,9,10,11, 12,13,14,15, 16,17,18,19,
                                       20,21,22,23, 24,25,26,27, 28,29,30,31, 4,5,6,7 };
    const int* map = (in_sizes[4] == 2*EMOL) ? setup_map : sig_map;
    #define IN(p) ((const float*)d_in[map[(p)]])
    #define INI(p) ((const int*)d_in[map[(p)]])

    const float *mol_x = IN(0), *prot_x = IN(1), *mol_eattr = IN(2), *prot_eattr = IN(3);
    const float *nlmW = IN(4), *nlmb = IN(5), *nlpW = IN(6), *nlpb = IN(7);
    const float *elmW = IN(8), *elmb = IN(9), *elpW = IN(10), *elpb = IN(11);
    const float *mcW1 = IN(12), *mcb1 = IN(13), *mcW2 = IN(14), *mcb2 = IN(15);
    const float *pcW1 = IN(16), *pcb1 = IN(17), *pcW2 = IN(18), *pcb2 = IN(19);
    const float *ampW = IN(20), *ampb = IN(21), *apmW = IN(22), *apmb = IN(23);
    const float *fc1W = IN(24), *fc1b = IN(25), *fc2W = IN(26), *fc2b = IN(27);
    const int *mei = INI(28), *pei = INI(29), *mbatch = INI(30), *pbatch = INI(31);
    float* out = (float*)d_out;

    float *xm, *xp, *em, *ep, *hm, *hp, *qb, *kb, *vb, *part, *pool, *cnt;
    cudaGetSymbolAddress((void**)&xm, g_xm);
    cudaGetSymbolAddress((void**)&xp, g_xp);
    cudaGetSymbolAddress((void**)&em, g_em);
    cudaGetSymbolAddress((void**)&ep, g_ep);
    cudaGetSymbolAddress((void**)&hm, g_hm);
    cudaGetSymbolAddress((void**)&hp, g_hp);
    cudaGetSymbolAddress((void**)&qb, g_q);
    cudaGetSymbolAddress((void**)&kb, g_k);
    cudaGetSymbolAddress((void**)&vb, g_v);
    cudaGetSymbolAddress((void**)&part, g_part);
    cudaGetSymbolAddress((void**)&pool, g_pool);
    cudaGetSymbolAddress((void**)&cnt, g_cnt);

    const int TB = 256;
    auto gblk = [](long n, int tb){ return (int)((n + tb - 1)/tb); };

    // --- node + edge embeddings
    linear_kernel<<<gblk((long)NMOL*HID, TB), TB>>>(mol_x,  nlmW, nlmb, xm, NMOL, 11);
    linear_kernel<<<gblk((long)NPROT*HID, TB), TB>>>(prot_x, nlpW, nlpb, xp, NPROT, 15);
    linear_kernel<<<gblk((long)EMOL*HID, TB), TB>>>(mol_eattr,  elmW, elmb, em, EMOL, 10);
    linear_kernel<<<gblk((long)EPROT*HID, TB), TB>>>(prot_eattr, elpW, elpb, ep, EPROT, 10);

    // --- 3 GINE layers each
    for (int l = 0; l < 3; l++) {
        copy_kernel<<<gblk((long)NMOL*HID, TB), TB>>>(hm, xm, NMOL*HID);
        msg_kernel<<<gblk((long)EMOL*HID, TB), TB>>>(xm, em, mei, hm, EMOL);
        gine_mlp<<<gblk(NMOL, MLP_ROWS), TB>>>(hm, mcW1 + l*4096, mcb1 + l*64,
                                               mcW2 + l*4096, mcb2 + l*64, xm, NMOL);
        copy_kernel<<<gblk((long)NPROT*HID, TB), TB>>>(hp, xp, NPROT*HID);
        msg_kernel<<<gblk((long)EPROT*HID, TB), TB>>>(xp, ep, pei, hp, EPROT);
        gine_mlp<<<gblk(NPROT, MLP_ROWS), TB>>>(hp, pcW1 + l*4096, pcb1 + l*64,
                                                pcW2 + l*4096, pcb2 + l*64, xp, NPROT);
    }

    // --- cross attention mol->prot (Q=mol, K/V=prot)
    linear_kernel<<<gblk((long)NMOL*HID, TB), TB>>>(xm, ampW,          ampb,       qb, NMOL, HID);
    linear_kernel<<<gblk((long)NPROT*HID, TB), TB>>>(xp, ampW + 4096,  ampb + 64,  kb, NPROT, HID);
    linear_kernel<<<gblk((long)NPROT*HID, TB), TB>>>(xp, ampW + 8192,  ampb + 128, vb, NPROT, HID);
    {
        dim3 grid(gblk(NMOL, QT), HEADS, SPLITS);
        flash_partial<<<grid, QT>>>(qb, kb, vb, NMOL, NPROT, NPROT/SPLITS, part);
        attn_combine<<<gblk((long)NMOL*HEADS, TB), TB>>>(part, xm, hm, NMOL);  // hm = H_mol
    }

    // --- cross attention prot->mol (Q=prot, K/V=mol)
    linear_kernel<<<gblk((long)NPROT*HID, TB), TB>>>(xp, apmW,         apmb,       qb, NPROT, HID);
    linear_kernel<<<gblk((long)NMOL*HID, TB), TB>>>(xm, apmW + 4096,   apmb + 64,  kb, NMOL, HID);
    linear_kernel<<<gblk((long)NMOL*HID, TB), TB>>>(xm, apmW + 8192,   apmb + 128, vb, NMOL, HID);
    {
        dim3 grid(gblk(NPROT, QT), HEADS, SPLITS);
        flash_partial<<<grid, QT>>>(qb, kb, vb, NPROT, NMOL, NMOL/SPLITS, part);
        attn_combine<<<gblk((long)NPROT*HEADS, TB), TB>>>(part, xp, hp, NPROT); // hp = H_prot
    }

    // --- pooling + head
    zero_kernel<<<gblk(BB*2*HID + 2*BB, TB), TB>>>(pool, BB*2*HID);   // pool then cnt (contiguous? no)
    zero_kernel<<<1, 64>>>(cnt, 2*BB);
    pool_kernel<<<gblk((long)NMOL*HID, TB), TB>>>(hm, mbatch, pool, cnt,      NMOL, 0);
    pool_kernel<<<gblk((long)NPROT*HID, TB), TB>>>(hp, pbatch, pool, cnt + BB, NPROT, HID);
    final_kernel<<<1, dim3(32, 32)>>>(pool, cnt, fc1W, fc1b, fc2W, fc2b, out);
}

// round 3
// speedup vs baseline: 1.1324x; 1.1324x over previous
#include <cuda_runtime.h>
#include <math.h>

#define HID   64
#define HEADS 4
#define HDIM  16
#define NMOL  2048
#define NPROT 4096
#define EMOL  32768
#define EPROT 131072
#define BB    32
#define SPLITS 8
#define QT    128   // threads / queries per flash block
#define KT    64    // key tile

typedef unsigned long long ull;

// ---------------- scratch (device globals; no allocation allowed) ------------
__device__ float g_xm[NMOL*HID];
__device__ float g_xp[NPROT*HID];
__device__ float g_em[EMOL*HID];
__device__ float g_ep[EPROT*HID];
__device__ float g_hm[NMOL*HID];
__device__ float g_hp[NPROT*HID];
__device__ float g_q[NPROT*HID];
__device__ float g_k[NPROT*HID];
__device__ float g_v[NPROT*HID];
__device__ float g_part[(size_t)NPROT*HEADS*SPLITS*18];
__device__ float g_pool[BB*2*HID];
__device__ float g_cnt[2*BB];
// CSR scratch
__device__ int g_mcnt[NMOL+1];
__device__ int g_moff[NMOL+1];
__device__ int g_mcur[NMOL];
__device__ int g_midx[EMOL];
__device__ int g_msrc[EMOL];
__device__ int g_pcnt[NPROT+1];
__device__ int g_poff[NPROT+1];
__device__ int g_pcur[NPROT];
__device__ int g_pidx[EPROT];
__device__ int g_psrc[EPROT];

// ---------------- f32x2 helpers ----------------------------------------------
__device__ __forceinline__ ull pk2(float a, float b) {
    ull r; asm("mov.b64 %0, {%1,%2};" : "=l"(r) : "f"(a), "f"(b)); return r;
}
__device__ __forceinline__ void upk2(float& a, float& b, ull r) {
    asm("mov.b64 {%0,%1}, %2;" : "=f"(a), "=f"(b) : "l"(r));
}
__device__ __forceinline__ ull ffma2(ull a, ull b, ull c) {
    ull d; asm("fma.rn.f32x2 %0, %1, %2, %3;" : "=l"(d) : "l"(a), "l"(b), "l"(c)); return d;
}
__device__ __forceinline__ ull fmul2(ull a, ull b) {
    ull d; asm("mul.rn.f32x2 %0, %1, %2;" : "=l"(d) : "l"(a), "l"(b)); return d;
}
union LD { float4 f4; ulonglong2 u2; };

// ---------------- fast linear: 4 outputs/thread, weights in SMEM -------------
__global__ void linear_fast(const float* __restrict__ in, const float* __restrict__ W,
                            const float* __restrict__ b, float* __restrict__ out,
                            int N, int K) {
    __shared__ float ws[64*64];
    __shared__ float bs[64];
    int tid = threadIdx.x;            // 256
    for (int i = tid; i < K*64; i += 256) ws[i] = W[i];
    if (tid < 64) bs[tid] = b[tid];
    __syncthreads();
    int idx = blockIdx.x*256 + tid;   // (n, c) with c in 0..15
    if (idx >= N*16) return;
    int n = idx >> 4, c = idx & 15;
    const float* inr = in + (size_t)n*K;
    float4 acc = ((const float4*)bs)[c];
    for (int k = 0; k < K; k++) {
        float iv = __ldg(inr + k);
        float4 w = ((const float4*)(ws + k*64))[c];
        acc.x = fmaf(iv, w.x, acc.x);
        acc.y = fmaf(iv, w.y, acc.y);
        acc.z = fmaf(iv, w.z, acc.z);
        acc.w = fmaf(iv, w.w, acc.w);
    }
    ((float4*)out)[idx] = acc;
}

// ---------------- CSR build ---------------------------------------------------
__global__ void zero_int(int* __restrict__ p, int n) {
    int i = blockIdx.x*blockDim.x + threadIdx.x;
    if (i < n) p[i] = 0;
}
__global__ void zero_float(float* __restrict__ p, int n) {
    int i = blockIdx.x*blockDim.x + threadIdx.x;
    if (i < n) p[i] = 0.f;
}
__global__ void hist_kernel(const int* __restrict__ dst, int* __restrict__ cnt, int E) {
    int e = blockIdx.x*blockDim.x + threadIdx.x;
    if (e < E) atomicAdd(&cnt[dst[e]], 1);
}
// single-block exclusive scan, N <= 4096, 1024 threads x 4 elems
__global__ void scan_kernel(const int* __restrict__ cnt, int* __restrict__ off,
                            int* __restrict__ cur, int N) {
    __shared__ int wsum[32];
    int t = threadIdx.x, lane = t & 31, wid = t >> 5;
    int base = t*4;
    int v[4];
    #pragma unroll
    for (int i = 0; i < 4; i++) v[i] = (base+i < N) ? cnt[base+i] : 0;
    int local = v[0]+v[1]+v[2]+v[3];
    int sc = local;
    #pragma unroll
    for (int o = 1; o < 32; o <<= 1) {
        int x = __shfl_up_sync(~0u, sc, o);
        if (lane >= o) sc += x;
    }
    if (lane == 31) wsum[wid] = sc;
    __syncthreads();
    if (wid == 0) {
        int x = wsum[lane];
        #pragma unroll
        for (int o = 1; o < 32; o <<= 1) {
            int y = __shfl_up_sync(~0u, x, o);
            if (lane >= o) x += y;
        }
        wsum[lane] = x;
    }
    __syncthreads();
    int excl = sc - local + (wid ? wsum[wid-1] : 0);
    #pragma unroll
    for (int i = 0; i < 4; i++) {
        if (base+i < N) { off[base+i] = excl; cur[base+i] = excl; }
        excl += v[i];
    }
    if (t == 1023) off[N] = wsum[31];
}
__global__ void scatter_kernel(const int* __restrict__ src, const int* __restrict__ dst,
                               int* __restrict__ cur, int* __restrict__ idx,
                               int* __restrict__ srcs, int E) {
    int e = blockIdx.x*blockDim.x + threadIdx.x;
    if (e >= E) return;
    int p = atomicAdd(&cur[dst[e]], 1);
    idx[p] = e;
    srcs[p] = src[e];
}

// ---------------- GINE gather: h[n] = x[n] + sum relu(x[src]+e) --------------
__global__ void gather_kernel(const float* __restrict__ x, const float* __restrict__ eattr,
                              const int* __restrict__ off, const int* __restrict__ idx,
                              const int* __restrict__ srcs, float* __restrict__ h, int N) {
    int n = blockIdx.x*4 + (threadIdx.x >> 6);   // 256 thr = 4 nodes x 64 feat
    int f = threadIdx.x & 63;
    if (n >= N) return;
    float acc = x[(size_t)n*HID + f];
    int jb = off[n], je = off[n+1];
    #pragma unroll 4
    for (int j = jb; j < je; j++) {
        int eid = idx[j];
        int s   = srcs[j];
        float v = x[(size_t)s*HID + f] + eattr[(size_t)eid*HID + f];
        acc += fmaxf(v, 0.f);
    }
    h[(size_t)n*HID + f] = acc;
}

// ---------------- GINE inner MLP: 16 rows/block, 4 outputs/thread -------------
#define MLP_ROWS 16
__global__ void gine_mlp(const float* __restrict__ h,
                         const float* __restrict__ W1, const float* __restrict__ b1,
                         const float* __restrict__ W2, const float* __restrict__ b2,
                         float* __restrict__ xout, int N) {
    __shared__ float w1s[64*64];
    __shared__ float w2s[64*64];
    __shared__ float hs[MLP_ROWS][64];
    __shared__ float ts[MLP_ROWS][64];
    int tid = threadIdx.x;               // 256
    for (int i = tid; i < 64*64; i += 256) { w1s[i] = W1[i]; w2s[i] = W2[i]; }
    int r = tid >> 4, c = tid & 15;      // r 0..15, c 0..15 (f = 4c)
    int row = blockIdx.x*MLP_ROWS + r;
    if (row < N) ((float4*)hs[r])[c] = ((const float4*)(h + (size_t)row*HID))[c];
    __syncthreads();
    float4 acc = ((const float4*)b1)[c];
    #pragma unroll
    for (int k = 0; k < 64; k++) {
        float hv = hs[r][k];
        float4 w = ((const float4*)(w1s + k*64))[c];
        acc.x = fmaf(hv, w.x, acc.x);
        acc.y = fmaf(hv, w.y, acc.y);
        acc.z = fmaf(hv, w.z, acc.z);
        acc.w = fmaf(hv, w.w, acc.w);
    }
    acc.x = fmaxf(acc.x, 0.f); acc.y = fmaxf(acc.y, 0.f);
    acc.z = fmaxf(acc.z, 0.f); acc.w = fmaxf(acc.w, 0.f);
    ((float4*)ts[r])[c] = acc;
    __syncthreads();
    float4 acc2 = ((const float4*)b2)[c];
    #pragma unroll
    for (int k = 0; k < 64; k++) {
        float hv = ts[r][k];
        float4 w = ((const float4*)(w2s + k*64))[c];
        acc2.x = fmaf(hv, w.x, acc2.x);
        acc2.y = fmaf(hv, w.y, acc2.y);
        acc2.z = fmaf(hv, w.z, acc2.z);
        acc2.w = fmaf(hv, w.w, acc2.w);
    }
    acc2.x = fmaxf(acc2.x, 0.f); acc2.y = fmaxf(acc2.y, 0.f);
    acc2.z = fmaxf(acc2.z, 0.f); acc2.w = fmaxf(acc2.w, 0.f);
    if (row < N) ((float4*)(xout + (size_t)row*HID))[c] = acc2;
}

// ---------------- flash attention, split-KV partials, f32x2 ------------------
__global__ void flash_partial(const float* __restrict__ Q, const float* __restrict__ K,
                              const float* __restrict__ V, int Nq, int Nk, int chunk,
                              float* __restrict__ part) {
    __shared__ float4 sk[KT][4];
    __shared__ float4 sv[KT][4];
    int h  = blockIdx.y;
    int sp = blockIdx.z;
    int q  = blockIdx.x*QT + threadIdx.x;
    int k0 = sp*chunk;
    int k1 = min(k0 + chunk, Nk);
    bool valid = q < Nq;
    ull q2[8];
    if (valid) {
        const float4* qp = (const float4*)(Q + (size_t)q*HID + h*HDIM);
        #pragma unroll
        for (int i = 0; i < 4; i++) {
            LD t; t.f4 = qp[i];
            q2[2*i] = t.u2.x; q2[2*i+1] = t.u2.y;
        }
    }
    float m = -1e30f, l = 0.f;
    ull o2[8];
    #pragma unroll
    for (int i = 0; i < 8; i++) o2[i] = 0ull;   // bits 0 == (0.f, 0.f)

    for (int kt = k0; kt < k1; kt += KT) {
        __syncthreads();
        for (int idx = threadIdx.x; idx < KT*4; idx += QT) {
            int row = idx >> 2, c = idx & 3;
            sk[row][c] = ((const float4*)(K + (size_t)(kt+row)*HID + h*HDIM))[c];
            sv[row][c] = ((const float4*)(V + (size_t)(kt+row)*HID + h*HDIM))[c];
        }
        __syncthreads();
        if (valid) {
            #pragma unroll 2
            for (int jj = 0; jj < KT; jj++) {
                LD kr[4];
                #pragma unroll
                for (int c = 0; c < 4; c++) kr[c].f4 = sk[jj][c];
                ull acc = 0ull;
                #pragma unroll
                for (int c = 0; c < 4; c++) {
                    acc = ffma2(q2[2*c],   kr[c].u2.x, acc);
                    acc = ffma2(q2[2*c+1], kr[c].u2.y, acc);
                }
                float lo, hi; upk2(lo, hi, acc);
                float s = (lo + hi) * 0.25f;
                if (s > m) {
                    float alpha = __expf(m - s);
                    l *= alpha;
                    ull a2 = pk2(alpha, alpha);
                    #pragma unroll
                    for (int i = 0; i < 8; i++) o2[i] = fmul2(o2[i], a2);
                    m = s;
                }
                float p = __expf(s - m);
                l += p;
                ull p2 = pk2(p, p);
                #pragma unroll
                for (int c = 0; c < 4; c++) {
                    LD vr; vr.f4 = sv[jj][c];
                    o2[2*c]   = ffma2(p2, vr.u2.x, o2[2*c]);
                    o2[2*c+1] = ffma2(p2, vr.u2.y, o2[2*c+1]);
                }
            }
        }
    }
    if (valid) {
        float* pp = part + (((size_t)q*HEADS + h)*SPLITS + sp)*18;
        pp[0] = m; pp[1] = l;
        #pragma unroll
        for (int i = 0; i < 8; i++) upk2(pp[2+2*i], pp[3+2*i], o2[i]);
    }
}

// ---------------- combine split-KV partials + residual -----------------------
__global__ void attn_combine(const float* __restrict__ part, const float* __restrict__ x,
                             float* __restrict__ H, int Nq) {
    int idx = blockIdx.x*blockDim.x + threadIdx.x;    // (q, head)
    if (idx >= Nq*HEADS) return;
    int q = idx / HEADS, h = idx % HEADS;
    const float* pp = part + (size_t)idx*SPLITS*18;
    float M = -1e30f;
    #pragma unroll
    for (int sp = 0; sp < SPLITS; sp++) M = fmaxf(M, pp[sp*18]);
    float L = 0.f;
    float O[HDIM];
    #pragma unroll
    for (int i = 0; i < HDIM; i++) O[i] = 0.f;
    #pragma unroll
    for (int sp = 0; sp < SPLITS; sp++) {
        float w = __expf(pp[sp*18] - M);
        L += w * pp[sp*18 + 1];
        #pragma unroll
        for (int i = 0; i < HDIM; i++) O[i] = fmaf(w, pp[sp*18 + 2 + i], O[i]);
    }
    float inv = 1.f / L;
    #pragma unroll
    for (int i = 0; i < HDIM; i++)
        H[(size_t)q*HID + h*HDIM + i] = x[(size_t)q*HID + h*HDIM + i] + O[i]*inv;
}

// ---------------- batched mean-pool (scatter) --------------------------------
__global__ void pool_kernel(const float* __restrict__ H, const int* __restrict__ batch,
                            float* __restrict__ pool, float* __restrict__ cnt,
                            int N, int colofs) {
    int idx = blockIdx.x*blockDim.x + threadIdx.x;
    if (idx >= N*HID) return;
    int n = idx >> 6, f = idx & 63;
    int b = batch[n];
    atomicAdd(&pool[b*(2*HID) + colofs + f], H[idx]);
    if (f == 0) atomicAdd(&cnt[b], 1.f);
}

// ---------------- head MLP ---------------------------------------------------
__global__ void final_kernel(const float* __restrict__ pool, const float* __restrict__ cnt,
                             const float* __restrict__ fc1W, const float* __restrict__ fc1b,
                             const float* __restrict__ fc2W, const float* __restrict__ fc2b,
                             float* __restrict__ out) {
    __shared__ float zs[BB][2*HID];
    int b = threadIdx.y;
    int lane = threadIdx.x;
    float cm = fmaxf(cnt[b],      1.f);
    float cp = fmaxf(cnt[BB + b], 1.f);
    for (int k = lane; k < 2*HID; k += 32) {
        float v = pool[b*(2*HID) + k];
        zs[b][k] = v / (k < HID ? cm : cp);
    }
    __syncwarp();
    float res = 0.f;
    for (int f0 = 0; f0 < HID; f0 += 32) {
        int f = f0 + lane;
        float acc = fc1b[f];
        for (int k = 0; k < 2*HID; k++) acc = fmaf(zs[b][k], fc1W[k*HID + f], acc);
        res += fmaxf(acc, 0.f) * fc2W[f];
    }
    #pragma unroll
    for (int off = 16; off; off >>= 1) res += __shfl_down_sync(0xffffffffu, res, off);
    if (lane == 0) out[b] = 1.f / (1.f + __expf(-(res + fc2b[0])));
}

// =============================================================================
extern "C" void kernel_launch(void* const* d_in, const int* in_sizes, int n_in,
                              void* d_out, int out_size) {
    static const int sig_map[32]   = { 0,1,2,3, 4,5,6,7, 8,9,10,11, 12,13,14,15,
                                       16,17,18,19, 20,21,22,23, 24,25,26,27, 28,29,30,31 };
    static const int setup_map[32] = { 0,1,2,3, 8,9,10,11, 12,13,14,15, 16,17,18,19,
                                       20,21,22,23, 24,25,26,27, 28,29,30,31, 4,5,6,7 };
    const int* map = (in_sizes[4] == 2*EMOL) ? setup_map : sig_map;
    #define IN(p) ((const float*)d_in[map[(p)]])
    #define INI(p) ((const int*)d_in[map[(p)]])

    const float *mol_x = IN(0), *prot_x = IN(1), *mol_eattr = IN(2), *prot_eattr = IN(3);
    const float *nlmW = IN(4), *nlmb = IN(5), *nlpW = IN(6), *nlpb = IN(7);
    const float *elmW = IN(8), *elmb = IN(9), *elpW = IN(10), *elpb = IN(11);
    const float *mcW1 = IN(12), *mcb1 = IN(13), *mcW2 = IN(14), *mcb2 = IN(15);
    const float *pcW1 = IN(16), *pcb1 = IN(17), *pcW2 = IN(18), *pcb2 = IN(19);
    const float *ampW = IN(20), *ampb = IN(21), *apmW = IN(22), *apmb = IN(23);
    const float *fc1W = IN(24), *fc1b = IN(25), *fc2W = IN(26), *fc2b = IN(27);
    const int *mei = INI(28), *pei = INI(29), *mbatch = INI(30), *pbatch = INI(31);
    float* out = (float*)d_out;

    float *xm, *xp, *em, *ep, *hm, *hp, *qb, *kb, *vb, *part, *pool, *cnt;
    int *mcnt, *moff, *mcur, *midx, *msrc, *pcnt, *poff, *pcur, *pidx, *psrc;
    cudaGetSymbolAddress((void**)&xm, g_xm);
    cudaGetSymbolAddress((void**)&xp, g_xp);
    cudaGetSymbolAddress((void**)&em, g_em);
    cudaGetSymbolAddress((void**)&ep, g_ep);
    cudaGetSymbolAddress((void**)&hm, g_hm);
    cudaGetSymbolAddress((void**)&hp, g_hp);
    cudaGetSymbolAddress((void**)&qb, g_q);
    cudaGetSymbolAddress((void**)&kb, g_k);
    cudaGetSymbolAddress((void**)&vb, g_v);
    cudaGetSymbolAddress((void**)&part, g_part);
    cudaGetSymbolAddress((void**)&pool, g_pool);
    cudaGetSymbolAddress((void**)&cnt, g_cnt);
    cudaGetSymbolAddress((void**)&mcnt, g_mcnt);
    cudaGetSymbolAddress((void**)&moff, g_moff);
    cudaGetSymbolAddress((void**)&mcur, g_mcur);
    cudaGetSymbolAddress((void**)&midx, g_midx);
    cudaGetSymbolAddress((void**)&msrc, g_msrc);
    cudaGetSymbolAddress((void**)&pcnt, g_pcnt);
    cudaGetSymbolAddress((void**)&poff, g_poff);
    cudaGetSymbolAddress((void**)&pcur, g_pcur);
    cudaGetSymbolAddress((void**)&pidx, g_pidx);
    cudaGetSymbolAddress((void**)&psrc, g_psrc);

    const int TB = 256;
    auto gblk = [](long n, int tb){ return (int)((n + tb - 1)/tb); };

    // --- CSR build (edges identical across layers; build once per launch)
    zero_int<<<gblk(NMOL+1, TB), TB>>>(mcnt, NMOL+1);
    zero_int<<<gblk(NPROT+1, TB), TB>>>(pcnt, NPROT+1);
    hist_kernel<<<gblk(EMOL, TB), TB>>>(mei + EMOL, mcnt, EMOL);
    hist_kernel<<<gblk(EPROT, TB), TB>>>(pei + EPROT, pcnt, EPROT);
    scan_kernel<<<1, 1024>>>(mcnt, moff, mcur, NMOL);
    scan_kernel<<<1, 1024>>>(pcnt, poff, pcur, NPROT);
    scatter_kernel<<<gblk(EMOL, TB), TB>>>(mei, mei + EMOL, mcur, midx, msrc, EMOL);
    scatter_kernel<<<gblk(EPROT, TB), TB>>>(pei, pei + EPROT, pcur, pidx, psrc, EPROT);

    // --- node + edge embeddings
    linear_fast<<<gblk((long)NMOL*16, TB), TB>>>(mol_x,  nlmW, nlmb, xm, NMOL, 11);
    linear_fast<<<gblk((long)NPROT*16, TB), TB>>>(prot_x, nlpW, nlpb, xp, NPROT, 15);
    linear_fast<<<gblk((long)EMOL*16, TB), TB>>>(mol_eattr,  elmW, elmb, em, EMOL, 10);
    linear_fast<<<gblk((long)EPROT*16, TB), TB>>>(prot_eattr, elpW, elpb, ep, EPROT, 10);

    // --- 3 GINE layers each (gather, no atomics)
    for (int l = 0; l < 3; l++) {
        gather_kernel<<<gblk(NMOL, 4), TB>>>(xm, em, moff, midx, msrc, hm, NMOL);
        gine_mlp<<<gblk(NMOL, MLP_ROWS), TB>>>(hm, mcW1 + l*4096, mcb1 + l*64,
                                               mcW2 + l*4096, mcb2 + l*64, xm, NMOL);
        gather_kernel<<<gblk(NPROT, 4), TB>>>(xp, ep, poff, pidx, psrc, hp, NPROT);
        gine_mlp<<<gblk(NPROT, MLP_ROWS), TB>>>(hp, pcW1 + l*4096, pcb1 + l*64,
                                                pcW2 + l*4096, pcb2 + l*64, xp, NPROT);
    }

    // --- cross attention mol->prot (Q=mol, K/V=prot)
    linear_fast<<<gblk((long)NMOL*16, TB), TB>>>(xm, ampW,         ampb,       qb, NMOL, HID);
    linear_fast<<<gblk((long)NPROT*16, TB), TB>>>(xp, ampW + 4096, ampb + 64,  kb, NPROT, HID);
    linear_fast<<<gblk((long)NPROT*16, TB), TB>>>(xp, ampW + 8192, ampb + 128, vb, NPROT, HID);
    {
        dim3 grid(gblk(NMOL, QT), HEADS, SPLITS);
        flash_partial<<<grid, QT>>>(qb, kb, vb, NMOL, NPROT, NPROT/SPLITS, part);
        attn_combine<<<gblk((long)NMOL*HEADS, TB), TB>>>(part, xm, hm, NMOL);  // hm = H_mol
    }

    // --- cross attention prot->mol (Q=prot, K/V=mol)
    linear_fast<<<gblk((long)NPROT*16, TB), TB>>>(xp, apmW,         apmb,       qb, NPROT, HID);
    linear_fast<<<gblk((long)NMOL*16, TB), TB>>>(xm, apmW + 4096,  apmb + 64,  kb, NMOL, HID);
    linear_fast<<<gblk((long)NMOL*16, TB), TB>>>(xm, apmW + 8192,  apmb + 128, vb, NMOL, HID);
    {
        dim3 grid(gblk(NPROT, QT), HEADS, SPLITS);
        flash_partial<<<grid, QT>>>(qb, kb, vb, NPROT, NMOL, NMOL/SPLITS, part);
        attn_combine<<<gblk((long)NPROT*HEADS, TB), TB>>>(part, xp, hp, NPROT); // hp = H_prot
    }

    // --- pooling + head
    zero_float<<<gblk(BB*2*HID, TB), TB>>>(pool, BB*2*HID);
    zero_float<<<1, 64>>>(cnt, 2*BB);
    pool_kernel<<<gblk((long)NMOL*HID, TB), TB>>>(hm, mbatch, pool, cnt,      NMOL, 0);
    pool_kernel<<<gblk((long)NPROT*HID, TB), TB>>>(hp, pbatch, pool, cnt + BB, NPROT, HID);
    final_kernel<<<1, dim3(32, 32)>>>(pool, cnt, fc1W, fc1b, fc2W, fc2b, out);
}

// round 5
// speedup vs baseline: 1.2759x; 1.1267x over previous
#include <cuda_runtime.h>
#include <math.h>

#define HID   64
#define HEADS 4
#define HDIM  16
#define NMOL  2048
#define NPROT 4096
#define EMOL  32768
#define EPROT 131072
#define BB    32
#define SPLITS 8
#define QT    128
#define KT    64

typedef unsigned long long ull;

// ---------------- scratch (device globals) -----------------------------------
__device__ float g_xm[NMOL*HID];
__device__ float g_xp[NPROT*HID];
__device__ float g_em[EMOL*HID];      // permuted (CSR slot order)
__device__ float g_ep[EPROT*HID];     // permuted
__device__ float g_hm[NMOL*HID];      // ping-pong partner of g_xm
__device__ float g_hp[NPROT*HID];     // ping-pong partner of g_xp
__device__ float g_q1[NMOL*HID];      // dir0: Q=mol
__device__ float g_k1[NPROT*HID];
__device__ float g_v1[NPROT*HID];
__device__ float g_q2[NPROT*HID];     // dir1: Q=prot
__device__ float g_k2[NMOL*HID];
__device__ float g_v2[NMOL*HID];
__device__ float g_part1[(size_t)NMOL*HEADS*SPLITS*18];
__device__ float g_part2[(size_t)NPROT*HEADS*SPLITS*18];
__device__ float g_pool[BB*2*HID];
// CSR scratch (zero-initialized at load; scan re-zeroes cnt each run)
__device__ int g_mcnt[NMOL+1];
__device__ int g_moff[NMOL+1];
__device__ int g_mcur[NMOL];
__device__ int g_msrc[EMOL];
__device__ int g_mpos[EMOL];
__device__ int g_pcnt[NPROT+1];
__device__ int g_poff[NPROT+1];
__device__ int g_pcur[NPROT];
__device__ int g_psrc[EPROT];
__device__ int g_ppos[EPROT];

// ---------------- f32x2 helpers ----------------------------------------------
__device__ __forceinline__ ull pk2(float a, float b) {
    ull r; asm("mov.b64 %0, {%1,%2};" : "=l"(r) : "f"(a), "f"(b)); return r;
}
__device__ __forceinline__ void upk2(float& a, float& b, ull r) {
    asm("mov.b64 {%0,%1}, %2;" : "=f"(a), "=f"(b) : "l"(r));
}
__device__ __forceinline__ ull ffma2(ull a, ull b, ull c) {
    ull d; asm("fma.rn.f32x2 %0, %1, %2, %3;" : "=l"(d) : "l"(a), "l"(b), "l"(c)); return d;
}
__device__ __forceinline__ ull fmul2(ull a, ull b) {
    ull d; asm("mul.rn.f32x2 %0, %1, %2;" : "=l"(d) : "l"(a), "l"(b)); return d;
}
union LD { float4 f4; ulonglong2 u2; };

// ---------------- CSR build: hist / scan / scatter (all fused mol+prot) ------
__global__ void hist_fused(const int* __restrict__ mdst, const int* __restrict__ pdst,
                           int* __restrict__ mcnt, int* __restrict__ pcnt) {
    int e = blockIdx.x*blockDim.x + threadIdx.x;
    if (e < EMOL) atomicAdd(&mcnt[mdst[e]], 1);
    else if (e < EMOL + EPROT) atomicAdd(&pcnt[pdst[e - EMOL]], 1);
}

// block 0: mol (N=2048), block 1: prot (N=4096). 1024 threads x 4 elems.
__global__ void scan_fused(int* __restrict__ mcnt, int* __restrict__ moff, int* __restrict__ mcur,
                           int* __restrict__ pcnt, int* __restrict__ poff, int* __restrict__ pcur) {
    int* cnt; int* off; int* cur; int N;
    if (blockIdx.x == 0) { cnt = mcnt; off = moff; cur = mcur; N = NMOL; }
    else                 { cnt = pcnt; off = poff; cur = pcur; N = NPROT; }
    __shared__ int wsum[32];
    int t = threadIdx.x, lane = t & 31, wid = t >> 5;
    int base = t*4;
    int v[4];
    #pragma unroll
    for (int i = 0; i < 4; i++) v[i] = (base+i < N) ? cnt[base+i] : 0;
    #pragma unroll
    for (int i = 0; i < 4; i++) if (base+i < N) cnt[base+i] = 0;   // re-zero for next run
    int local = v[0]+v[1]+v[2]+v[3];
    int sc = local;
    #pragma unroll
    for (int o = 1; o < 32; o <<= 1) {
        int x = __shfl_up_sync(~0u, sc, o);
        if (lane >= o) sc += x;
    }
    if (lane == 31) wsum[wid] = sc;
    __syncthreads();
    if (wid == 0) {
        int x = wsum[lane];
        #pragma unroll
        for (int o = 1; o < 32; o <<= 1) {
            int y = __shfl_up_sync(~0u, x, o);
            if (lane >= o) x += y;
        }
        wsum[lane] = x;
    }
    __syncthreads();
    int excl = sc - local + (wid ? wsum[wid-1] : 0);
    #pragma unroll
    for (int i = 0; i < 4; i++) {
        if (base+i < N) { off[base+i] = excl; cur[base+i] = excl; }
        excl += v[i];
    }
    if (t == 1023) off[N] = wsum[31];
}

__global__ void scatter_fused(const int* __restrict__ mei, const int* __restrict__ pei,
                              int* __restrict__ mcur, int* __restrict__ msrc, int* __restrict__ mpos,
                              int* __restrict__ pcur, int* __restrict__ psrc, int* __restrict__ ppos) {
    int e = blockIdx.x*blockDim.x + threadIdx.x;
    if (e < EMOL) {
        int p = atomicAdd(&mcur[mei[EMOL + e]], 1);
        msrc[p] = mei[e];
        mpos[e] = p;
    } else if (e < EMOL + EPROT) {
        int ee = e - EMOL;
        int p = atomicAdd(&pcur[pei[EPROT + ee]], 1);
        psrc[p] = pei[ee];
        ppos[ee] = p;
    }
}

// ---------------- fused embeddings (4 linears, edge outputs permuted) --------
struct EmbedArgs {
    const float* in[4]; const float* W[4]; const float* b[4];
    float* out[4]; const int* pos[4]; int K[4]; int ofs[5];
};
__global__ void embed_fused(EmbedArgs a) {
    __shared__ float ws[15*64];
    __shared__ float bs[64];
    int bid = blockIdx.x;
    int t;
    if      (bid < a.ofs[1]) t = 0;
    else if (bid < a.ofs[2]) t = 1;
    else if (bid < a.ofs[3]) t = 2;
    else                     t = 3;
    int K = a.K[t];
    int tid = threadIdx.x;
    for (int i = tid; i < K*64; i += 256) ws[i] = a.W[t][i];
    if (tid < 64) bs[tid] = a.b[t][tid];
    __syncthreads();
    int idx = (bid - a.ofs[t])*256 + tid;
    int n = idx >> 4, c = idx & 15;
    const float* inr = a.in[t] + (size_t)n*K;
    float4 acc = ((const float4*)bs)[c];
    for (int k = 0; k < K; k++) {
        float iv = __ldg(inr + k);
        float4 w = ((const float4*)(ws + k*64))[c];
        acc.x = fmaf(iv, w.x, acc.x);
        acc.y = fmaf(iv, w.y, acc.y);
        acc.z = fmaf(iv, w.z, acc.z);
        acc.w = fmaf(iv, w.w, acc.w);
    }
    int orow = a.pos[t] ? a.pos[t][n] : n;
    ((float4*)a.out[t])[(size_t)orow*16 + c] = acc;
}

// ---------------- fused GINE layer: gather + 2-layer MLP, mol+prot ----------
// NOTE: xin and xout MUST be different buffers (blocks read remote nodes).
struct GineArgs {
    const float* x[2]; const float* e[2];
    const int* off[2]; const int* srcs[2];
    const float* W1[2]; const float* b1[2]; const float* W2[2]; const float* b2[2];
    float* xout[2]; int nblk0;
};
__global__ void gine_fused(GineArgs a) {
    __shared__ float w1s[64*64];
    __shared__ float w2s[64*64];
    __shared__ float hs[16][64];
    __shared__ float ts[16][64];
    int g = (blockIdx.x < a.nblk0) ? 0 : 1;
    int bbase = ((g ? blockIdx.x - a.nblk0 : blockIdx.x)) * 16;
    int tid = threadIdx.x;     // 256
    for (int i = tid; i < 64*64; i += 256) { w1s[i] = a.W1[g][i]; w2s[i] = a.W2[g][i]; }
    const float* x    = a.x[g];
    const float* e    = a.e[g];
    const int*   off  = a.off[g];
    const int*   srcs = a.srcs[g];
    // gather: 4 nodes in parallel x 4 iterations = 16 nodes
    int f = tid & 63, rg = tid >> 6;
    #pragma unroll
    for (int i = 0; i < 4; i++) {
        int r = i*4 + rg;
        int node = bbase + r;
        float acc = x[(size_t)node*HID + f];
        int jb = off[node], je = off[node+1];
        #pragma unroll 4
        for (int j = jb; j < je; j++) {
            float v = x[(size_t)srcs[j]*HID + f] + e[(size_t)j*HID + f];
            acc += fmaxf(v, 0.f);
        }
        hs[r][f] = acc;
    }
    __syncthreads();
    // MLP: 16 rows, 4 outputs/thread
    int r = tid >> 4, c = tid & 15;
    float4 acc = ((const float4*)a.b1[g])[c];
    #pragma unroll
    for (int k = 0; k < 64; k++) {
        float hv = hs[r][k];
        float4 w = ((const float4*)(w1s + k*64))[c];
        acc.x = fmaf(hv, w.x, acc.x);
        acc.y = fmaf(hv, w.y, acc.y);
        acc.z = fmaf(hv, w.z, acc.z);
        acc.w = fmaf(hv, w.w, acc.w);
    }
    acc.x = fmaxf(acc.x, 0.f); acc.y = fmaxf(acc.y, 0.f);
    acc.z = fmaxf(acc.z, 0.f); acc.w = fmaxf(acc.w, 0.f);
    ((float4*)ts[r])[c] = acc;
    __syncthreads();
    float4 acc2 = ((const float4*)a.b2[g])[c];
    #pragma unroll
    for (int k = 0; k < 64; k++) {
        float hv = ts[r][k];
        float4 w = ((const float4*)(w2s + k*64))[c];
        acc2.x = fmaf(hv, w.x, acc2.x);
        acc2.y = fmaf(hv, w.y, acc2.y);
        acc2.z = fmaf(hv, w.z, acc2.z);
        acc2.w = fmaf(hv, w.w, acc2.w);
    }
    acc2.x = fmaxf(acc2.x, 0.f); acc2.y = fmaxf(acc2.y, 0.f);
    acc2.z = fmaxf(acc2.z, 0.f); acc2.w = fmaxf(acc2.w, 0.f);
    ((float4*)(a.xout[g] + (size_t)(bbase + r)*HID))[c] = acc2;
}

// ---------------- fused QKV linears (6 tasks, K=64) --------------------------
struct QKVArgs {
    const float* in[6]; const float* W[6]; const float* b[6];
    float* out[6]; int ofs[7];
};
__global__ void qkv_fused(QKVArgs a) {
    __shared__ float ws[64*64];
    __shared__ float bs[64];
    int bid = blockIdx.x;
    int t = 5;
    #pragma unroll
    for (int i = 5; i >= 1; i--) if (bid < a.ofs[i]) t = i - 1;
    int tid = threadIdx.x;
    for (int i = tid; i < 64*64; i += 256) ws[i] = a.W[t][i];
    if (tid < 64) bs[tid] = a.b[t][tid];
    __syncthreads();
    int idx = (bid - a.ofs[t])*256 + tid;
    int n = idx >> 4, c = idx & 15;
    const float* inr = a.in[t] + (size_t)n*HID;
    float4 acc = ((const float4*)bs)[c];
    #pragma unroll 8
    for (int k = 0; k < 64; k++) {
        float iv = __ldg(inr + k);
        float4 w = ((const float4*)(ws + k*64))[c];
        acc.x = fmaf(iv, w.x, acc.x);
        acc.y = fmaf(iv, w.y, acc.y);
        acc.z = fmaf(iv, w.z, acc.z);
        acc.w = fmaf(iv, w.w, acc.w);
    }
    ((float4*)a.out[t])[(size_t)n*16 + c] = acc;
}

// ---------------- flash attention, both directions, split-KV, f32x2 ----------
__global__ void flash_fused(const float* __restrict__ Q1, const float* __restrict__ K1,
                            const float* __restrict__ V1, const float* __restrict__ Q2,
                            const float* __restrict__ K2, const float* __restrict__ V2,
                            float* __restrict__ part1, float* __restrict__ part2) {
    __shared__ float4 sk[KT][4];
    __shared__ float4 sv[KT][4];
    const float *Q, *K, *V; float* part; int Nk, qblk;
    if (blockIdx.x < NMOL/QT) { Q = Q1; K = K1; V = V1; part = part1; Nk = NPROT; qblk = blockIdx.x; }
    else                      { Q = Q2; K = K2; V = V2; part = part2; Nk = NMOL;  qblk = blockIdx.x - NMOL/QT; }
    int h  = blockIdx.y;
    int sp = blockIdx.z;
    int chunk = Nk / SPLITS;
    int q  = qblk*QT + threadIdx.x;
    int k0 = sp*chunk;
    int k1 = k0 + chunk;
    ull q2[8];
    {
        const float4* qp = (const float4*)(Q + (size_t)q*HID + h*HDIM);
        #pragma unroll
        for (int i = 0; i < 4; i++) {
            LD t; t.f4 = qp[i];
            q2[2*i] = t.u2.x; q2[2*i+1] = t.u2.y;
        }
    }
    float m = -1e30f, l = 0.f;
    ull o2[8];
    #pragma unroll
    for (int i = 0; i < 8; i++) o2[i] = 0ull;

    for (int kt = k0; kt < k1; kt += KT) {
        __syncthreads();
        for (int idx = threadIdx.x; idx < KT*4; idx += QT) {
            int row = idx >> 2, c = idx & 3;
            sk[row][c] = ((const float4*)(K + (size_t)(kt+row)*HID + h*HDIM))[c];
            sv[row][c] = ((const float4*)(V + (size_t)(kt+row)*HID + h*HDIM))[c];
        }
        __syncthreads();
        #pragma unroll 2
        for (int jj = 0; jj < KT; jj++) {
            LD kr[4];
            #pragma unroll
            for (int c = 0; c < 4; c++) kr[c].f4 = sk[jj][c];
            ull acc = 0ull;
            #pragma unroll
            for (int c = 0; c < 4; c++) {
                acc = ffma2(q2[2*c],   kr[c].u2.x, acc);
                acc = ffma2(q2[2*c+1], kr[c].u2.y, acc);
            }
            float lo, hi; upk2(lo, hi, acc);
            float s = (lo + hi) * 0.25f;
            if (s > m) {
                float alpha = __expf(m - s);
                l *= alpha;
                ull a2 = pk2(alpha, alpha);
                #pragma unroll
                for (int i = 0; i < 8; i++) o2[i] = fmul2(o2[i], a2);
                m = s;
            }
            float p = __expf(s - m);
            l += p;
            ull p2 = pk2(p, p);
            #pragma unroll
            for (int c = 0; c < 4; c++) {
                LD vr; vr.f4 = sv[jj][c];
                o2[2*c]   = ffma2(p2, vr.u2.x, o2[2*c]);
                o2[2*c+1] = ffma2(p2, vr.u2.y, o2[2*c+1]);
            }
        }
    }
    float* pp = part + (((size_t)q*HEADS + h)*SPLITS + sp)*18;
    pp[0] = m; pp[1] = l;
    #pragma unroll
    for (int i = 0; i < 8; i++) upk2(pp[2+2*i], pp[3+2*i], o2[i]);
}

// ---------------- combine split-KV partials + residual (both dirs) -----------
__global__ void combine_fused(const float* __restrict__ part1, const float* __restrict__ part2,
                              const float* __restrict__ xm, const float* __restrict__ xp,
                              float* __restrict__ Hm, float* __restrict__ Hp) {
    int idx = blockIdx.x*blockDim.x + threadIdx.x;
    const float* part; const float* x; float* H;
    if (idx < NMOL*HEADS) { part = part1; x = xm; H = Hm; }
    else { idx -= NMOL*HEADS; if (idx >= NPROT*HEADS) return; part = part2; x = xp; H = Hp; }
    int q = idx >> 2, h = idx & 3;
    const float* pp = part + (size_t)idx*SPLITS*18;
    float M = -1e30f;
    #pragma unroll
    for (int sp = 0; sp < SPLITS; sp++) M = fmaxf(M, pp[sp*18]);
    float L = 0.f;
    float O[HDIM];
    #pragma unroll
    for (int i = 0; i < HDIM; i++) O[i] = 0.f;
    #pragma unroll
    for (int sp = 0; sp < SPLITS; sp++) {
        float w = __expf(pp[sp*18] - M);
        L += w * pp[sp*18 + 1];
        #pragma unroll
        for (int i = 0; i < HDIM; i++) O[i] = fmaf(w, pp[sp*18 + 2 + i], O[i]);
    }
    float inv = 1.f / L;
    #pragma unroll
    for (int i = 0; i < HDIM; i++)
        H[(size_t)q*HID + h*HDIM + i] = x[(size_t)q*HID + h*HDIM + i] + O[i]*inv;
}

// ---------------- pooling via sorted-segment reduction (no atomics) ----------
__global__ void pool_fused(const float* __restrict__ Hm, const float* __restrict__ Hp,
                           const int* __restrict__ mbatch, const int* __restrict__ pbatch,
                           float* __restrict__ pool) {
    int b = blockIdx.x & 31;
    int side = blockIdx.x >> 5;
    const float* H = side ? Hp : Hm;
    const int* batch = side ? pbatch : mbatch;
    int N = side ? NPROT : NMOL;
    int lo = 0, hi = N;
    while (lo < hi) { int mid = (lo+hi) >> 1; if (batch[mid] < b) lo = mid+1; else hi = mid; }
    int lo2 = lo, hi2 = N;
    while (lo2 < hi2) { int mid = (lo2+hi2) >> 1; if (batch[mid] < b+1) lo2 = mid+1; else hi2 = mid; }
    int f = threadIdx.x;
    float s = 0.f;
    for (int r = lo; r < lo2; r++) s += H[(size_t)r*HID + f];
    float c = (float)(lo2 - lo);
    pool[b*(2*HID) + side*HID + f] = s / fmaxf(c, 1.f);
}

// ---------------- head MLP (pool already contains means) ---------------------
__global__ void final_kernel(const float* __restrict__ pool,
                             const float* __restrict__ fc1W, const float* __restrict__ fc1b,
                             const float* __restrict__ fc2W, const float* __restrict__ fc2b,
                             float* __restrict__ out) {
    __shared__ float zs[BB][2*HID];
    int b = threadIdx.y;
    int lane = threadIdx.x;
    for (int k = lane; k < 2*HID; k += 32) zs[b][k] = pool[b*(2*HID) + k];
    __syncwarp();
    float res = 0.f;
    for (int f0 = 0; f0 < HID; f0 += 32) {
        int f = f0 + lane;
        float acc = fc1b[f];
        for (int k = 0; k < 2*HID; k++) acc = fmaf(zs[b][k], fc1W[k*HID + f], acc);
        res += fmaxf(acc, 0.f) * fc2W[f];
    }
    #pragma unroll
    for (int off = 16; off; off >>= 1) res += __shfl_down_sync(0xffffffffu, res, off);
    if (lane == 0) out[b] = 1.f / (1.f + __expf(-(res + fc2b[0])));
}

// =============================================================================
extern "C" void kernel_launch(void* const* d_in, const int* in_sizes, int n_in,
                              void* d_out, int out_size) {
    static const int sig_map[32]   = { 0,1,2,3, 4,5,6,7, 8,9,10,11, 12,13,14,15,
                                       16,17,18,19, 20,21,22,23, 24,25,26,27, 28,29,30,31 };
    static const int setup_map[32] = { 0,1,2,3, 8,9,10,11, 12,13,14,15, 16,17,18,19,
                                       20,21,22,23, 24,25,26,27, 28,29,30,31, 4,5,6,7 };
    const int* map = (in_sizes[4] == 2*EMOL) ? setup_map : sig_map;
    #define IN(p) ((const float*)d_in[map[(p)]])
    #define INI(p) ((const int*)d_in[map[(p)]])

    const float *mol_x = IN(0), *prot_x = IN(1), *mol_eattr = IN(2), *prot_eattr = IN(3);
    const float *nlmW = IN(4), *nlmb = IN(5), *nlpW = IN(6), *nlpb = IN(7);
    const float *elmW = IN(8), *elmb = IN(9), *elpW = IN(10), *elpb = IN(11);
    const float *mcW1 = IN(12), *mcb1 = IN(13), *mcW2 = IN(14), *mcb2 = IN(15);
    const float *pcW1 = IN(16), *pcb1 = IN(17), *pcW2 = IN(18), *pcb2 = IN(19);
    const float *ampW = IN(20), *ampb = IN(21), *apmW = IN(22), *apmb = IN(23);
    const float *fc1W = IN(24), *fc1b = IN(25), *fc2W = IN(26), *fc2b = IN(27);
    const int *mei = INI(28), *pei = INI(29), *mbatch = INI(30), *pbatch = INI(31);
    float* out = (float*)d_out;

    float *xm, *xp, *em, *ep, *hm, *hp, *q1, *k1, *v1, *q2, *k2, *v2, *part1, *part2, *pool;
    int *mcnt, *moff, *mcur, *msrc, *mpos, *pcnt, *poff, *pcur, *psrc, *ppos;
    cudaGetSymbolAddress((void**)&xm, g_xm);
    cudaGetSymbolAddress((void**)&xp, g_xp);
    cudaGetSymbolAddress((void**)&em, g_em);
    cudaGetSymbolAddress((void**)&ep, g_ep);
    cudaGetSymbolAddress((void**)&hm, g_hm);
    cudaGetSymbolAddress((void**)&hp, g_hp);
    cudaGetSymbolAddress((void**)&q1, g_q1);
    cudaGetSymbolAddress((void**)&k1, g_k1);
    cudaGetSymbolAddress((void**)&v1, g_v1);
    cudaGetSymbolAddress((void**)&q2, g_q2);
    cudaGetSymbolAddress((void**)&k2, g_k2);
    cudaGetSymbolAddress((void**)&v2, g_v2);
    cudaGetSymbolAddress((void**)&part1, g_part1);
    cudaGetSymbolAddress((void**)&part2, g_part2);
    cudaGetSymbolAddress((void**)&pool, g_pool);
    cudaGetSymbolAddress((void**)&mcnt, g_mcnt);
    cudaGetSymbolAddress((void**)&moff, g_moff);
    cudaGetSymbolAddress((void**)&mcur, g_mcur);
    cudaGetSymbolAddress((void**)&msrc, g_msrc);
    cudaGetSymbolAddress((void**)&mpos, g_mpos);
    cudaGetSymbolAddress((void**)&pcnt, g_pcnt);
    cudaGetSymbolAddress((void**)&poff, g_poff);
    cudaGetSymbolAddress((void**)&pcur, g_pcur);
    cudaGetSymbolAddress((void**)&psrc, g_psrc);
    cudaGetSymbolAddress((void**)&ppos, g_ppos);

    const int TB = 256;

    // --- 1-3: CSR build
    hist_fused<<<(EMOL + EPROT + TB - 1)/TB, TB>>>(mei + EMOL, pei + EPROT, mcnt, pcnt);
    scan_fused<<<2, 1024>>>(mcnt, moff, mcur, pcnt, poff, pcur);
    scatter_fused<<<(EMOL + EPROT + TB - 1)/TB, TB>>>(mei, pei, mcur, msrc, mpos, pcur, psrc, ppos);

    // --- 4: all embeddings (edge outputs in CSR order)
    {
        EmbedArgs a;
        a.in[0] = mol_x;     a.W[0] = nlmW; a.b[0] = nlmb; a.out[0] = xm; a.pos[0] = nullptr; a.K[0] = 11;
        a.in[1] = prot_x;    a.W[1] = nlpW; a.b[1] = nlpb; a.out[1] = xp; a.pos[1] = nullptr; a.K[1] = 15;
        a.in[2] = mol_eattr; a.W[2] = elmW; a.b[2] = elmb; a.out[2] = em; a.pos[2] = mpos;    a.K[2] = 10;
        a.in[3] = prot_eattr;a.W[3] = elpW; a.b[3] = elpb; a.out[3] = ep; a.pos[3] = ppos;    a.K[3] = 10;
        a.ofs[0] = 0; a.ofs[1] = NMOL/16; a.ofs[2] = a.ofs[1] + NPROT/16;
        a.ofs[3] = a.ofs[2] + EMOL/16; a.ofs[4] = a.ofs[3] + EPROT/16;
        embed_fused<<<a.ofs[4], TB>>>(a);
    }

    // --- 5-7: GINE layers, PING-PONG buffers (in != out: blocks read remote nodes)
    // l0: xm->hm, l1: hm->xm, l2: xm->hm. Final conv features live in hm/hp.
    for (int l = 0; l < 3; l++) {
        const float* im = (l & 1) ? hm : xm;
        const float* ip = (l & 1) ? hp : xp;
        float* om = (l & 1) ? xm : hm;
        float* op = (l & 1) ? xp : hp;
        GineArgs a;
        a.x[0] = im; a.e[0] = em; a.off[0] = moff; a.srcs[0] = msrc;
        a.W1[0] = mcW1 + l*4096; a.b1[0] = mcb1 + l*64; a.W2[0] = mcW2 + l*4096; a.b2[0] = mcb2 + l*64;
        a.xout[0] = om;
        a.x[1] = ip; a.e[1] = ep; a.off[1] = poff; a.srcs[1] = psrc;
        a.W1[1] = pcW1 + l*4096; a.b1[1] = pcb1 + l*64; a.W2[1] = pcW2 + l*4096; a.b2[1] = pcb2 + l*64;
        a.xout[1] = op;
        a.nblk0 = NMOL/16;
        gine_fused<<<NMOL/16 + NPROT/16, TB>>>(a);
    }
    // post-conv features: hm (mol), hp (prot)

    // --- 8: all six QKV linears (inputs hm/hp)
    {
        QKVArgs a;
        a.in[0] = hm; a.W[0] = ampW;        a.b[0] = ampb;       a.out[0] = q1;  // Q1 (mol)
        a.in[1] = hp; a.W[1] = ampW + 4096; a.b[1] = ampb + 64;  a.out[1] = k1;  // K1 (prot)
        a.in[2] = hp; a.W[2] = ampW + 8192; a.b[2] = ampb + 128; a.out[2] = v1;  // V1 (prot)
        a.in[3] = hp; a.W[3] = apmW;        a.b[3] = apmb;       a.out[3] = q2;  // Q2 (prot)
        a.in[4] = hm; a.W[4] = apmW + 4096; a.b[4] = apmb + 64;  a.out[4] = k2;  // K2 (mol)
        a.in[5] = hm; a.W[5] = apmW + 8192; a.b[5] = apmb + 128; a.out[5] = v2;  // V2 (mol)
        int nb[6] = { NMOL/16, NPROT/16, NPROT/16, NPROT/16, NMOL/16, NMOL/16 };
        a.ofs[0] = 0;
        for (int i = 0; i < 6; i++) a.ofs[i+1] = a.ofs[i] + nb[i];
        qkv_fused<<<a.ofs[6], TB>>>(a);
    }

    // --- 9: flash attention, both directions
    {
        dim3 grid(NMOL/QT + NPROT/QT, HEADS, SPLITS);
        flash_fused<<<grid, QT>>>(q1, k1, v1, q2, k2, v2, part1, part2);
    }

    // --- 10: combine + residual (x = hm/hp), H written into now-free xm/xp
    combine_fused<<<((NMOL + NPROT)*HEADS + TB - 1)/TB, TB>>>(part1, part2, hm, hp, xm, xp);

    // --- 11-12: pooling + head (H_mol = xm, H_prot = xp)
    pool_fused<<<64, 64>>>(xm, xp, mbatch, pbatch, pool);
    final_kernel<<<1, dim3(32, 32)>>>(pool, fc1W, fc1b, fc2W, fc2b, out);
}